// round 6
// baseline (speedup 1.0000x reference)
#include <cuda_runtime.h>
#include <cstdint>

#define DIM 64
#define KCODES 1024
#define NROWS (32*64*64)
#define QELEMS (NROWS*DIM)
#define THRESH 1e-4f

// smem word layout for vq_mma: se[1024] | 2 bufs x (2 splits x 128 codes x 68)
#define SE_W   1024
#define BUF_W  17408          // 2*128*68
#define SPL_W  8704           // 128*68
#define SMEM_W (SE_W + 2*BUF_W)

__device__ float g_se[KCODES];
__device__ float g_bsplit[2][KCODES][68];   // prefragged: [g*8+q*2+half] = e[8g+q+4*half]
__device__ float4 g_res[NROWS];             // {best, second, idx_bits, 0}
__device__ float g_losspart[512];

__device__ __forceinline__ uint32_t s2u(const void* p){
    uint32_t a; asm("{ .reg .u64 t; cvta.to.shared.u64 t, %1; cvt.u32.u64 %0, t; }":"=r"(a):"l"(p)); return a;
}
__device__ __forceinline__ void mma_t(float& d0, float& d1, float& d2, float& d3,
                                      uint32_t a0, uint32_t a1, uint32_t a2, uint32_t a3,
                                      uint32_t b0, uint32_t b1) {
    asm("mma.sync.aligned.m16n8k8.row.col.f32.tf32.tf32.f32 "
        "{%0,%1,%2,%3},{%4,%5,%6,%7},{%8,%9},{%0,%1,%2,%3};"
        : "+f"(d0), "+f"(d1), "+f"(d2), "+f"(d3)
        : "r"(a0), "r"(a1), "r"(a2), "r"(a3), "r"(b0), "r"(b1));
}
#define CPA16(dst, src) asm volatile("cp.async.cg.shared.global [%0], [%1], 16;"::"r"(dst),"l"(src):"memory")
#define CPCOMMIT()      asm volatile("cp.async.commit_group;":::"memory")
#define CPWAIT(n)       asm volatile("cp.async.wait_group %0;"::"n"(n):"memory")

// ------------------- prep: se + pre-split pre-fragged codebook -------------
__global__ void vq_prep(const float* __restrict__ cb) {
    int k = blockIdx.x * blockDim.x + threadIdx.x;
    if (k >= KCODES) return;
    float s = 0.f;
#pragma unroll
    for (int c = 0; c < DIM; ++c) {
        float v = cb[k*DIM + c];
        s = fmaf(v, v, s);
        float hi = __uint_as_float(__float_as_uint(v) & 0xFFFFE000u);
        int g = c >> 3, k8 = c & 7, q = k8 & 3, half = k8 >> 2;
        int pos = g*8 + q*2 + half;
        g_bsplit[0][k][pos] = hi;
        g_bsplit[1][k][pos] = v - hi;
    }
    g_se[k] = s;
}

// ------------------- main: split-tf32 mma.sync scan ------------------------
__global__ __launch_bounds__(512, 1) void vq_mma(const float* __restrict__ x) {
    extern __shared__ float sm[];
    const uint32_t sb = s2u(sm);
    const int tid = threadIdx.x, w = tid>>5, lane = tid&31;
    const int gid = lane>>2, tig = lane&3;
    const int n0 = blockIdx.x * 256;            // 256 rows per CTA
    const int b = n0 >> 12, hw0 = n0 & 4095;

    // se -> smem
    for (int i = tid; i < KCODES; i += 512) sm[i] = g_se[i];

    // kick chunk 0 B-load
    {
        for (int i = tid; i < 4352; i += 512) {
            int split = i / 2176, rem = i % 2176, n = rem / 17, j = (rem % 17) * 4;
            uint32_t dst = sb + 4*(SE_W + split*SPL_W + n*68 + j);
            CPA16(dst, (const void*)&g_bsplit[split][n][j]);
        }
        CPCOMMIT();
    }

    // A fragments in registers: rows r0 = w*16+gid, r1 = r0+8
    const int r0 = w*16 + gid;
    uint32_t ah[8][4], al[8][4];
    const float* xb = x + (size_t)b*262144 + hw0;
#pragma unroll
    for (int g = 0; g < 8; ++g) {
        int k0 = 8*g + tig;
#pragma unroll
        for (int j = 0; j < 4; ++j) {
            int k = k0 + (j >> 1)*4;            // j:0,1 -> k0 ; j:2,3 -> k0+4
            int r = r0 + (j & 1)*8;             // j even -> r0 ; odd -> r1
            float v = xb[k*4096 + r];
            float hi = __uint_as_float(__float_as_uint(v) & 0xFFFFE000u);
            // frag order: a0=(r0,k0) a1=(r1,k0) a2=(r0,k0+4) a3=(r1,k0+4)
            ah[g][j] = __float_as_uint(hi);
            al[g][j] = __float_as_uint(v - hi);
        }
    }

    float d1a = 3e38f, d2a = 3e38f, d1b = 3e38f, d2b = 3e38f;
    int ka = 0, kb = 0;

    for (int c = 0; c < 8; ++c) {
        int buf = c & 1;
        if (c < 7) {                            // prefetch next chunk
            int nb = (c+1) & 1, base = (c+1)*128;
            for (int i = tid; i < 4352; i += 512) {
                int split = i / 2176, rem = i % 2176, n = rem / 17, j = (rem % 17) * 4;
                uint32_t dst = sb + 4*(SE_W + nb*BUF_W + split*SPL_W + n*68 + j);
                CPA16(dst, (const void*)&g_bsplit[split][base + n][j]);
            }
            CPCOMMIT();
            CPWAIT(1);
        } else {
            CPWAIT(0);
        }
        __syncthreads();

        const float* bh_base = sm + SE_W + buf*BUF_W;
        const float* bl_base = bh_base + SPL_W;
#pragma unroll 2
        for (int t = 0; t < 16; ++t) {
            int nrow = t*8 + gid;               // this thread's B column (code)
            const float2* bh = reinterpret_cast<const float2*>(bh_base + nrow*68 + tig*2);
            const float2* bl = reinterpret_cast<const float2*>(bl_base + nrow*68 + tig*2);
            float d0 = 0.f, d1 = 0.f, d2 = 0.f, d3 = 0.f;
#pragma unroll
            for (int g = 0; g < 8; ++g) {
                float2 h2 = bh[g*4];            // (e[8g+tig], e[8g+tig+4])
                float2 l2 = bl[g*4];
                uint32_t b0 = __float_as_uint(h2.x), b1 = __float_as_uint(h2.y);
                uint32_t c0 = __float_as_uint(l2.x), c1 = __float_as_uint(l2.y);
                mma_t(d0,d1,d2,d3, ah[g][0],ah[g][1],ah[g][2],ah[g][3], b0,b1);
                mma_t(d0,d1,d2,d3, ah[g][0],ah[g][1],ah[g][2],ah[g][3], c0,c1);
                mma_t(d0,d1,d2,d3, al[g][0],al[g][1],al[g][2],al[g][3], b0,b1);
            }
            // scores: s = se - 2P ; frag d0=(r0,c0) d1=(r0,c0+1) d2=(r1,c0) d3=(r1,c0+1)
            int kg = c*128 + t*8 + tig*2;
            float2 sep = *reinterpret_cast<const float2*>(sm + kg);
            float s0 = fmaf(d0, -2.f, sep.x);
            float s1 = fmaf(d1, -2.f, sep.y);
            float s2 = fmaf(d2, -2.f, sep.x);
            float s3 = fmaf(d3, -2.f, sep.y);
            if (s0 < d1a) { d2a = d1a; d1a = s0; ka = kg; } else if (s0 < d2a) d2a = s0;
            if (s1 < d1a) { d2a = d1a; d1a = s1; ka = kg+1; } else if (s1 < d2a) d2a = s1;
            if (s2 < d1b) { d2b = d1b; d1b = s2; kb = kg; } else if (s2 < d2b) d2b = s2;
            if (s3 < d1b) { d2b = d1b; d1b = s3; kb = kg+1; } else if (s3 < d2b) d2b = s3;
        }
        __syncthreads();
    }

    // merge across the 4 threads of each output quad (lanes gid*4 + tig)
    const unsigned FULL = 0xffffffffu;
#pragma unroll
    for (int o = 1; o <= 2; o <<= 1) {
        float od1 = __shfl_xor_sync(FULL, d1a, o), od2 = __shfl_xor_sync(FULL, d2a, o);
        int   ok  = __shfl_xor_sync(FULL, ka, o);
        if (od1 < d1a || (od1 == d1a && ok < ka)) { d2a = fminf(d1a, od2); d1a = od1; ka = ok; }
        else d2a = fminf(d2a, od1);
        od1 = __shfl_xor_sync(FULL, d1b, o); od2 = __shfl_xor_sync(FULL, d2b, o);
        ok  = __shfl_xor_sync(FULL, kb, o);
        if (od1 < d1b || (od1 == d1b && ok < kb)) { d2b = fminf(d1b, od2); d1b = od1; kb = ok; }
        else d2b = fminf(d2b, od1);
    }
    if (tig == 0) {
        g_res[n0 + r0]     = make_float4(d1a, d2a, __int_as_float(ka), 0.f);
        g_res[n0 + r0 + 8] = make_float4(d1b, d2b, __int_as_float(kb), 0.f);
    }
}

// ------------------- finalize: exact rescue + outputs ----------------------
__global__ __launch_bounds__(256) void vq_fin(const float* __restrict__ x,
                                              const float* __restrict__ cb,
                                              float* __restrict__ out) {
    __shared__ float xs[8][64];
    __shared__ float red[256];
    const int tid = threadIdx.x, lane = tid&31, wrp = tid>>5;
    const int n = blockIdx.x*256 + tid;
    const unsigned FULL = 0xffffffffu;

    float4 rs = g_res[n];
    int bi = __float_as_int(rs.z);
    int flag = (rs.y - rs.x) < THRESH;
    unsigned m = __ballot_sync(FULL, flag);
    while (m) {
        int src = __ffs(m)-1; m &= m-1;
        int rn = __shfl_sync(FULL, n, src);
        int bb = rn>>12, hw = rn&4095;
        const float* xr = x + (size_t)bb*262144 + hw;
        for (int c = lane; c < 64; c += 32) xs[wrp][c] = xr[c*4096];
        __syncwarp();
        float sx = 0.f;
#pragma unroll
        for (int c = 0; c < 64; ++c) sx = fmaf(xs[wrp][c], xs[wrp][c], sx);
        float bd = 3e38f; int bk = 0;
        for (int k0 = 0; k0 < 32; ++k0) {
            int k = lane*32 + k0;
            const float* e = cb + k*64;
            float P = 0.f;
#pragma unroll
            for (int c = 0; c < 64; ++c) P = fmaf(xs[wrp][c], e[c], P);   // ref chain
            float d = __fadd_rn(__fadd_rn(sx, g_se[k]), __fmul_rn(-2.0f, P));
            if (d < bd) { bd = d; bk = k; }
        }
#pragma unroll
        for (int o = 16; o > 0; o >>= 1) {
            float dv = __shfl_down_sync(FULL, bd, o);
            int   kv = __shfl_down_sync(FULL, bk, o);
            if (dv < bd || (dv == bd && kv < bk)) { bd = dv; bk = kv; }
        }
        int win = __shfl_sync(FULL, bk, 0);
        if (lane == src) bi = win;
        __syncwarp();
    }

    const int bb = n>>12, hw = n&4095;
    const float* xr = x + (size_t)bb*262144 + hw;
    const float* e  = cb + bi*64;
    float* q = out + 1 + (size_t)bb*262144 + hw;
    float lsum = 0.f;
#pragma unroll
    for (int c = 0; c < 64; ++c) {
        float ec = __ldg(e + c);
        float d  = ec - xr[c*4096];
        lsum = fmaf(d, d, lsum);
        q[c*4096] = ec;
    }
    out[1 + QELEMS + n] = (float)bi;

    red[tid] = lsum;
    __syncthreads();
#pragma unroll
    for (int s = 128; s > 0; s >>= 1) {
        if (tid < s) red[tid] += red[tid + s];
        __syncthreads();
    }
    if (tid == 0) g_losspart[blockIdx.x] = red[0];
}

__global__ void vq_loss(float* __restrict__ out) {
    __shared__ float red[512];
    int tid = threadIdx.x;
    red[tid] = g_losspart[tid];
    __syncthreads();
    for (int s = 256; s > 0; s >>= 1) {
        if (tid < s) red[tid] += red[tid + s];
        __syncthreads();
    }
    if (tid == 0) out[0] = red[0] * (1.25f / (float)QELEMS);
}

extern "C" void kernel_launch(void* const* d_in, const int* in_sizes, int n_in,
                              void* d_out, int out_size) {
    const float* x  = (const float*)d_in[0];
    const float* cb = (const float*)d_in[1];
    float* out = (float*)d_out;
    cudaFuncSetAttribute(vq_mma, cudaFuncAttributeMaxDynamicSharedMemorySize, SMEM_W*4);
    vq_prep<<<4, 256>>>(cb);
    vq_mma<<<NROWS/256, 512, SMEM_W*4>>>(x);
    vq_fin<<<NROWS/256, 256>>>(x, cb, out);
    vq_loss<<<1, 512>>>(out);
}